// round 2
// baseline (speedup 1.0000x reference)
#include <cuda_runtime.h>

// SIR scan: state (S,I,R) per batch row, 2048 sequential steps, controls (beta,gamma).
// (B,T,F) = (16384, 2048, 2) fp32. Each thread owns one batch row and streams its
// contiguous 16KB of controls with register double-buffering (32 steps / 256B per chunk)
// to keep ~16 outstanding 16B loads per thread -> saturate HBM despite only 512 warps.

#define TT    2048
#define FF    2
#define CHUNK 32                   // timesteps per prefetch chunk
#define V4    (CHUNK * FF / 4)     // 16 float4 per chunk
#define NCH   (TT / CHUNK)         // 64 chunks

#define POPULATION 1000000.0f

__device__ __forceinline__ void sir_step(float& S, float& I, float& R,
                                         float beta, float gamma) {
    // match reference expression order: beta * S * I / POPULATION (left-assoc)
    float new_inf = beta * S * I / POPULATION;
    float new_rec = gamma * I;
    S = S - new_inf;
    I = I + new_inf - new_rec;
    R = R + new_rec;
}

__global__ __launch_bounds__(64, 1)
void sir_scan_kernel(const float* __restrict__ in,     // (B, T, F)
                     const float* __restrict__ init,   // (B, 3)
                     float* __restrict__ out,          // copies x (B, 3)
                     int B, int copies) {
    int b = blockIdx.x * blockDim.x + threadIdx.x;
    if (b >= B) return;

    const float4* row = reinterpret_cast<const float4*>(in) + (size_t)b * (TT * FF / 4);

    float S = init[3 * b + 0];
    float I = init[3 * b + 1];
    float R = init[3 * b + 2];

    float4 cur[V4], nxt[V4];

#pragma unroll
    for (int j = 0; j < V4; j++) cur[j] = row[j];

    for (int c = 0; c < NCH - 1; c++) {
        const float4* nrow = row + (size_t)(c + 1) * V4;
        // prefetch next chunk (independent of the recurrence chain below)
#pragma unroll
        for (int j = 0; j < V4; j++) nxt[j] = nrow[j];
        // consume current chunk: each float4 = 2 timesteps (b0,g0,b1,g1)
#pragma unroll
        for (int j = 0; j < V4; j++) {
            float4 u = cur[j];
            sir_step(S, I, R, u.x, u.y);
            sir_step(S, I, R, u.z, u.w);
        }
#pragma unroll
        for (int j = 0; j < V4; j++) cur[j] = nxt[j];
    }
    // last chunk (no prefetch past end of row)
#pragma unroll
    for (int j = 0; j < V4; j++) {
        float4 u = cur[j];
        sir_step(S, I, R, u.x, u.y);
        sir_step(S, I, R, u.z, u.w);
    }

    // reference returns (final_state, final_state): replicate per out_size
    for (int k = 0; k < copies; k++) {
        float* o = out + (size_t)k * (size_t)B * 3 + 3 * b;
        o[0] = S;
        o[1] = I;
        o[2] = R;
    }
}

extern "C" void kernel_launch(void* const* d_in, const int* in_sizes, int n_in,
                              void* d_out, int out_size) {
    const float* in   = (const float*)d_in[0];   // inputs (B,T,F) fp32
    const float* init = (const float*)d_in[1];   // initial_state (B,3) fp32
    float* out = (float*)d_out;

    int B = in_sizes[1] / 3;
    int copies = out_size / (B * 3);
    if (copies < 1) copies = 1;

    const int threads = 64;  // 256 blocks -> all 148 SMs participate
    int blocks = (B + threads - 1) / threads;
    sir_scan_kernel<<<blocks, threads>>>(in, init, out, B, copies);
}

// round 5
// speedup vs baseline: 5.2464x; 5.2464x over previous
#include <cuda_runtime.h>

// SIR scan, (B,T,F) = (16384, 2048, 2) fp32, 2048 sequential steps per batch row.
// One thread per row; contiguous 16KB stream per thread with register
// double-buffering (32 steps / 16 x float4 per chunk).
//
// Critical-path engineering: the carried recurrence through (S, I) is reduced
// to 2 dependent FFMAs per step (8 cyc steady state). beta/POPULATION is folded
// into an off-chain FMUL on the freshly loaded control. No divide anywhere.

#define TT    2048
#define FF    2
#define CHUNK 32                   // timesteps per prefetch chunk
#define V4    (CHUNK * FF / 4)     // 16 float4 per chunk
#define NCH   (TT / CHUNK)         // 64 chunks

#define INV_POP 1e-6f

__device__ __forceinline__ void sir_step(float& S, float& I, float& R,
                                         float beta, float gamma) {
    float bp = beta * INV_POP;           // off-chain: depends only on loaded data
    float a  = bp * S;                   // chain: S + 4
    float Sn = __fmaf_rn(-a, I, S);      // S - new_inf
    float t  = __fmaf_rn( a, I, I);      // I + new_inf
    float In = __fmaf_rn(-gamma, I, t);  // I + new_inf - new_rec
    R = __fmaf_rn(gamma, I, R);          // off-chain accumulator
    S = Sn;
    I = In;
}

__global__ __launch_bounds__(64, 1)
void sir_scan_kernel(const float* __restrict__ in,     // (B, T, F)
                     const float* __restrict__ init,   // (B, 3)
                     float* __restrict__ out,          // copies x (B, 3)
                     int B, int copies) {
    int b = blockIdx.x * blockDim.x + threadIdx.x;
    if (b >= B) return;

    const float4* row = reinterpret_cast<const float4*>(in) + (size_t)b * (TT * FF / 4);

    float S = init[3 * b + 0];
    float I = init[3 * b + 1];
    float R = init[3 * b + 2];

    float4 cur[V4], nxt[V4];

#pragma unroll
    for (int j = 0; j < V4; j++) cur[j] = row[j];

#pragma unroll 2
    for (int c = 0; c < NCH - 1; c++) {
        const float4* nrow = row + (size_t)(c + 1) * V4;
        // prefetch next chunk (independent of the recurrence chain below)
#pragma unroll
        for (int j = 0; j < V4; j++) nxt[j] = nrow[j];
        // consume current chunk: each float4 = 2 timesteps (b0,g0,b1,g1)
#pragma unroll
        for (int j = 0; j < V4; j++) {
            float4 u = cur[j];
            sir_step(S, I, R, u.x, u.y);
            sir_step(S, I, R, u.z, u.w);
        }
#pragma unroll
        for (int j = 0; j < V4; j++) cur[j] = nxt[j];
    }
    // last chunk
#pragma unroll
    for (int j = 0; j < V4; j++) {
        float4 u = cur[j];
        sir_step(S, I, R, u.x, u.y);
        sir_step(S, I, R, u.z, u.w);
    }

    // reference returns (final_state, final_state): replicate per out_size
    for (int k = 0; k < copies; k++) {
        float* o = out + (size_t)k * (size_t)B * 3 + 3 * b;
        o[0] = S;
        o[1] = I;
        o[2] = R;
    }
}

extern "C" void kernel_launch(void* const* d_in, const int* in_sizes, int n_in,
                              void* d_out, int out_size) {
    const float* in   = (const float*)d_in[0];   // inputs (B,T,F) fp32
    const float* init = (const float*)d_in[1];   // initial_state (B,3) fp32
    float* out = (float*)d_out;

    int B = in_sizes[1] / 3;
    int copies = out_size / (B * 3);
    if (copies < 1) copies = 1;

    const int threads = 64;  // 256 blocks -> all SMs participate
    int blocks = (B + threads - 1) / threads;
    sir_scan_kernel<<<blocks, threads>>>(in, init, out, B, copies);
}

// round 6
// speedup vs baseline: 8.0822x; 1.5405x over previous
#include <cuda_runtime.h>

// SIR scan, (B,T,F) = (16384, 2048, 2) fp32, 2048 sequential steps per row.
// R5 finding: per-thread row streaming makes every warp LDG touch 32 distinct
// 128B lines -> L1tex wavefront-bound (L1=69%, DRAM=39%). Fix: stage chunks
// through shared memory with cp.async using a coalesced 16-lanes-per-row
// mapping (4 wavefronts/warp-load instead of 32), double-buffered; compute
// reads smem via a 68-float padded stride (conflict-free LDS.128).

#define TT       2048
#define FF       2
#define CHUNK    32                   // timesteps per chunk
#define ROWV4    (CHUNK * FF / 4)     // 16 float4 per row-chunk (256 B)
#define NCH      (TT / CHUNK)         // 64 chunks
#define BDIM     64                   // threads per block = rows per block
#define STR_V4   17                   // padded row stride in float4 (68 floats)
#define ROW_STR4 (TT * FF / 4)        // 1024 float4 per global row

#define INV_POP 1e-6f

__device__ __forceinline__ void cp_async16(float4* smem_dst, const float4* gmem_src) {
    unsigned s = (unsigned)__cvta_generic_to_shared(smem_dst);
    asm volatile("cp.async.cg.shared.global [%0], [%1], 16;\n" :: "r"(s), "l"(gmem_src));
}

__device__ __forceinline__ void sir_step(float& S, float& I, float& R,
                                         float beta, float gamma) {
    float bp = beta * INV_POP;           // off-chain
    float a  = bp * S;                   // chain: +4
    float Sn = __fmaf_rn(-a, I, S);      // chain: +4
    float t  = __fmaf_rn( a, I, I);      // chain: +4 (parallel with Sn)
    float In = __fmaf_rn(-gamma, I, t);  // chain: +4
    R = __fmaf_rn(gamma, I, R);          // off-chain accumulator
    S = Sn;
    I = In;
}

__global__ __launch_bounds__(BDIM, 2)
void sir_scan_kernel(const float* __restrict__ in,     // (B, T, F)
                     const float* __restrict__ init,   // (B, 3)
                     float* __restrict__ out,          // copies x (B, 3)
                     int B, int copies) {
    __shared__ float4 buf[2][BDIM * STR_V4];   // 2 x 17408 B

    const int tid  = threadIdx.x;
    const int row0 = blockIdx.x * BDIM;
    const int b    = row0 + tid;

    const float4* gin = reinterpret_cast<const float4*>(in);

    float S = 0.f, I = 0.f, R = 0.f;
    if (b < B) {
        S = init[3 * b + 0];
        I = init[3 * b + 1];
        R = init[3 * b + 2];
    }

    // Coalesced staging map: slot s = k*BDIM + tid; 16 consecutive lanes cover
    // one row's 256 B chunk -> each warp instruction = 2 rows x 2 lines = 4 wf.
    // Precompute per-thread (row, off) pairs' global bases.
    const float4* gbase[ROWV4];
    float4*       sdst0[ROWV4];
    float4*       sdst1[ROWV4];
#pragma unroll
    for (int k = 0; k < ROWV4; k++) {
        int s   = k * BDIM + tid;
        int row = s >> 4;          // 0..63
        int off = s & 15;          // 0..15
        int gr  = row0 + row;
        if (gr >= B) gr = B - 1;   // clamp (B divisible by 64 in practice)
        gbase[k] = gin + (size_t)gr * ROW_STR4 + off;
        sdst0[k] = &buf[0][row * STR_V4 + off];
        sdst1[k] = &buf[1][row * STR_V4 + off];
    }

    // Prologue: stage chunk 0 into buf0
#pragma unroll
    for (int k = 0; k < ROWV4; k++) cp_async16(sdst0[k], gbase[k]);
    asm volatile("cp.async.commit_group;\n" ::);

    for (int c = 0; c < NCH; c++) {
        // issue next chunk into the other buffer
        if (c + 1 < NCH) {
            float4** sd = ((c + 1) & 1) ? sdst1 : sdst0;
#pragma unroll
            for (int k = 0; k < ROWV4; k++)
                cp_async16(sd[k], gbase[k] + (size_t)(c + 1) * ROWV4);
            asm volatile("cp.async.commit_group;\n" ::);
            asm volatile("cp.async.wait_group 1;\n" ::);
        } else {
            asm volatile("cp.async.wait_group 0;\n" ::);
        }
        __syncthreads();

        // consume chunk c: thread reads its own padded smem row (conflict-free)
        const float4* cb = &buf[c & 1][tid * STR_V4];
#pragma unroll
        for (int j = 0; j < ROWV4; j++) {
            float4 u = cb[j];
            sir_step(S, I, R, u.x, u.y);
            sir_step(S, I, R, u.z, u.w);
        }
        __syncthreads();   // before this buffer is overwritten two iterations later
    }

    if (b < B) {
        for (int k = 0; k < copies; k++) {
            float* o = out + (size_t)k * (size_t)B * 3 + 3 * b;
            o[0] = S;
            o[1] = I;
            o[2] = R;
        }
    }
}

extern "C" void kernel_launch(void* const* d_in, const int* in_sizes, int n_in,
                              void* d_out, int out_size) {
    const float* in   = (const float*)d_in[0];   // inputs (B,T,F) fp32
    const float* init = (const float*)d_in[1];   // initial_state (B,3) fp32
    float* out = (float*)d_out;

    int B = in_sizes[1] / 3;
    int copies = out_size / (B * 3);
    if (copies < 1) copies = 1;

    int blocks = (B + BDIM - 1) / BDIM;          // 256 blocks of 64 threads
    sir_scan_kernel<<<blocks, BDIM>>>(in, init, out, B, copies);
}